// round 11
// baseline (speedup 1.0000x reference)
#include <cuda_runtime.h>
#include <cuda_bf16.h>

// SSIM loss: inputs (16,3,512,512) fp32 x2, output scalar fp32.
// Separable 11-tap Gaussian; 4 conv fields {a, b, (a+b)^2, (a-b)^2}:
//   sigma1+sigma2 = (Ep+Em)/2 - mu1^2 - mu2^2,  sigma12 = (Ep-Em)/4 - mu1*mu2.
//
// R10: R7 geometry (TX=64, TY=32, 16-row phase-A strips = best measured
// instructions/pixel) + in-kernel last-block finalization (R9 win) +
// templated y-interior fast path (no per-row bounds checks on 14/16 rows).

#define W_IMG 512
#define H_IMG 512
#define PLANE (512 * 512)
#define TX 64
#define TY 32
#define HC (TX + 10)               // 74 halo cols
#define SVS 75                     // smem row stride (75 mod 32 = 11, odd -> CF)
#define GX (W_IMG / TX)            // 8
#define GY (H_IMG / TY)            // 16
#define N_BLOCKS (GX * GY * 48)    // 6144
#define N_PIX 12582912.0

__device__ float g_part[N_BLOCKS];
__device__ unsigned int g_count;   // zero-init; self-resetting

// Gaussian window, sigma=1.5, ws=11, normalized. Function-local, constant
// indices after unroll -> FFMA with immediate multiplier (rt_SMSP=1).
#define DECL_GW()                                                        \
    const float GW[11] = {                                               \
        0.00102838f, 0.00759876f, 0.03600077f, 0.10936069f, 0.21300554f, \
        0.26601173f,                                                     \
        0.21300554f, 0.10936069f, 0.03600077f, 0.00759876f, 0.00102838f }

__device__ __forceinline__ float clip01(float v) {
    return fminf(fmaxf(v, 0.0f), 1.0f);   // fmaxf(NaN,0)=0 handles nan_to_num
}

// Vertical 11-tap pass over one column strip (16 output rows, 26 input rows).
// CHECK_Y=false: all 26 input rows known in-bounds (no per-row predicate).
template <bool CHECK_Y>
__device__ __forceinline__ void vert_strip(
    const float* __restrict__ A, const float* __restrict__ B,
    int gc, bool okc, int gr0 /* first input row = cy0+r0-5 */,
    float (&acc0)[16], float (&acc1)[16], float (&acc2)[16], float (&acc3)[16])
{
    DECL_GW();
    #pragma unroll
    for (int r = 0; r < 16; r++) {
        acc0[r] = 0.0f; acc1[r] = 0.0f; acc2[r] = 0.0f; acc3[r] = 0.0f;
    }
    #pragma unroll
    for (int q = 0; q < 26; q++) {
        float a = 0.0f, b = 0.0f;
        if (CHECK_Y) {
            const int gr = gr0 + q;
            if (okc && (unsigned)gr < (unsigned)H_IMG) {
                const int idx = gr * W_IMG + gc;
                a = A[idx];
                b = B[idx];
            }
        } else {
            if (okc) {
                const int idx = (gr0 + q) * W_IMG + gc;
                a = A[idx];
                b = B[idx];
            }
        }
        a = clip01(a);
        b = clip01(b);
        const float s = a + b, d = a - b;
        const float p = s * s, m = d * d;
        #pragma unroll
        for (int rr = (q > 10 ? q - 10 : 0); rr <= (q < 15 ? q : 15); rr++) {
            const float w = GW[q - rr];              // immediate
            acc0[rr] = fmaf(a, w, acc0[rr]);
            acc1[rr] = fmaf(b, w, acc1[rr]);
            acc2[rr] = fmaf(p, w, acc2[rr]);
            acc3[rr] = fmaf(m, w, acc3[rr]);
        }
    }
}

extern __shared__ float smem_raw[];
// layout: sV[4][TY][SVS] | red[8]

__global__ __launch_bounds__(256, 2)
void ssim_main_kernel(const float* __restrict__ img1,
                      const float* __restrict__ img2,
                      float* __restrict__ out) {
    DECL_GW();
    float* sV0 = smem_raw;                 // vertically filtered: a
    float* sV1 = sV0 + TY * SVS;           // b
    float* sV2 = sV1 + TY * SVS;           // (a+b)^2
    float* sV3 = sV2 + TY * SVS;           // (a-b)^2
    float* red = sV3 + TY * SVS;
    __shared__ unsigned int s_is_last;
    __shared__ double dred[8];

    const int tid   = threadIdx.x;
    const int plane = blockIdx.z;
    const int cx0   = blockIdx.x * TX;
    const int cy0   = blockIdx.y * TY;
    const float* __restrict__ A = img1 + (size_t)plane * PLANE;
    const float* __restrict__ B = img2 + (size_t)plane * PLANE;

    // ---------------- Phase A: vertical 11-tap conv ----------------
    // 74 halo cols x 2 strips of 16 output rows = 148 work items.
    if (tid < 2 * HC) {
        const int col   = (tid < HC) ? tid : tid - HC;
        const int strip = (tid < HC) ? 0 : 1;
        const int r0    = strip * 16;
        const int gc    = cx0 + col - 5;
        const bool okc  = ((unsigned)gc < (unsigned)W_IMG);
        const int gr0   = cy0 + r0 - 5;

        float acc0[16], acc1[16], acc2[16], acc3[16];
        // Whole block y-interior: first input row >= 0 and last (cy0+36+... )
        // max gr over both strips = cy0 + 16 + 25 - 5 = cy0 + 36 <= 511.
        if (cy0 >= 5 && cy0 <= H_IMG - 37) {
            vert_strip<false>(A, B, gc, okc, gr0, acc0, acc1, acc2, acc3);
        } else {
            vert_strip<true>(A, B, gc, okc, gr0, acc0, acc1, acc2, acc3);
        }
        #pragma unroll
        for (int rr = 0; rr < 16; rr++) {
            const int o = (r0 + rr) * SVS + col;
            sV0[o] = acc0[rr];
            sV1[o] = acc1[rr];
            sV2[o] = acc2[rr];
            sV3[o] = acc3[rr];
        }
    }
    __syncthreads();

    // ---------------- Phase B: horizontal conv + SSIM ----------------
    // warp = 32 consecutive rows of one 8-col group; stride 75 -> CF LDS.
    const int orow = tid & 31;        // 0..31
    const int grp  = tid >> 5;        // 0..7
    const int base = orow * SVS + grp * 8;

    float acc0[8], acc1[8], acc2[8], acc3[8];
    #pragma unroll
    for (int o = 0; o < 8; o++) {
        acc0[o] = 0.0f; acc1[o] = 0.0f; acc2[o] = 0.0f; acc3[o] = 0.0f;
    }

    #pragma unroll
    for (int p = 0; p < 18; p++) {
        const float v0 = sV0[base + p];
        const float v1 = sV1[base + p];
        const float v2 = sV2[base + p];
        const float v3 = sV3[base + p];
        #pragma unroll
        for (int o = (p > 10 ? p - 10 : 0); o <= (p < 7 ? p : 7); o++) {
            const float w = GW[p - o];
            acc0[o] = fmaf(v0, w, acc0[o]);
            acc1[o] = fmaf(v1, w, acc1[o]);
            acc2[o] = fmaf(v2, w, acc2[o]);
            acc3[o] = fmaf(v3, w, acc3[o]);
        }
    }

    const float C1 = 0.000101f;   // 0.01^2 + 1e-6
    const float C2 = 0.000901f;   // 0.03^2 + 1e-6
    float lsum = 0.0f;
    #pragma unroll
    for (int o = 0; o < 8; o++) {
        const float mu1 = acc0[o], mu2 = acc1[o];
        const float Ep = acc2[o], Em = acc3[o];
        const float mu1s = mu1 * mu1;
        const float mu2s = mu2 * mu2;
        const float mu12 = mu1 * mu2;
        const float musum = mu1s + mu2s;
        const float ssum = fmaf(0.5f, Ep + Em, -musum);  // sigma1+sigma2
        const float s12  = fmaf(0.25f, Ep - Em, -mu12);  // sigma12
        const float num = fmaf(2.0f, mu12, C1) * fmaf(2.0f, s12, C2);
        const float den = (musum + C1) * (ssum + C2);
        lsum += __fdividef(num, den);
    }

    // ---------------- Block reduction -> partial sum ----------------
    #pragma unroll
    for (int off = 16; off > 0; off >>= 1)
        lsum += __shfl_xor_sync(0xffffffffu, lsum, off);

    const int warp = tid >> 5;
    const int lane = tid & 31;
    if (lane == 0) red[warp] = lsum;
    __syncthreads();

    const int bid = (blockIdx.z * GY + blockIdx.y) * GX + blockIdx.x;
    if (tid == 0) {
        float v = 0.0f;
        #pragma unroll
        for (int i = 0; i < 8; i++) v += red[i];
        g_part[bid] = v;
        __threadfence();
        const unsigned int c = atomicAdd(&g_count, 1u);
        s_is_last = (c == (unsigned)(N_BLOCKS - 1)) ? 1u : 0u;
    }
    __syncthreads();

    // ---------------- Last block: final reduction ----------------
    if (s_is_last) {
        const float4* p4 = (const float4*)g_part;    // 6144/4 = 1536
        double s = 0.0;
        for (int i = tid; i < N_BLOCKS / 4; i += 256) {
            const float4 v = p4[i];
            s += (double)v.x + (double)v.y + (double)v.z + (double)v.w;
        }
        #pragma unroll
        for (int off = 16; off > 0; off >>= 1)
            s += __shfl_xor_sync(0xffffffffu, s, off);
        if (lane == 0) dred[warp] = s;
        __syncthreads();
        if (warp == 0) {
            double v = (lane < 8) ? dred[lane] : 0.0;
            #pragma unroll
            for (int off = 4; off > 0; off >>= 1)
                v += __shfl_xor_sync(0xffffffffu, v, off);
            if (lane == 0) {
                out[0] = (float)(1.0 - v / N_PIX);
                g_count = 0;                 // reset for next replay
            }
        }
    }
}

extern "C" void kernel_launch(void* const* d_in, const int* in_sizes, int n_in,
                              void* d_out, int out_size) {
    const float* img1 = (const float*)d_in[0];
    const float* img2 = (const float*)d_in[1];
    float* out = (float*)d_out;

    const int smem_bytes = (4 * TY * SVS + 8) * 4;   // ~38.4 KB
    cudaFuncSetAttribute(ssim_main_kernel,
                         cudaFuncAttributeMaxDynamicSharedMemorySize,
                         smem_bytes);

    dim3 grid(GX, GY, 48);   // 8 x 16 x 48 = 6144 blocks
    ssim_main_kernel<<<grid, 256, smem_bytes>>>(img1, img2, out);
}

// round 15
// speedup vs baseline: 1.0633x; 1.0633x over previous
#include <cuda_runtime.h>
#include <cuda_bf16.h>

// SSIM loss: inputs (16,3,512,512) fp32 x2, output scalar fp32.
// Separable 11-tap Gaussian; 4 conv fields {a, b, (a+b)^2, (a-b)^2}:
//   sigma1+sigma2 = (Ep+Em)/2 - mu1^2 - mu2^2,  sigma12 = (Ep-Em)/4 - mu1*mu2.
//
// R11: exact R7 compute body (single-path phase A, 72 regs, best measured
// main-kernel time) + in-kernel last-block finalization (removes the 9us
// fini kernel). Nothing else.

#define W_IMG 512
#define H_IMG 512
#define PLANE (512 * 512)
#define TX 64
#define TY 32
#define HC (TX + 10)               // 74 halo cols
#define SVS 75                     // smem row stride (75 mod 32 = 11 -> CF)
#define GX (W_IMG / TX)            // 8
#define GY (H_IMG / TY)            // 16
#define N_BLOCKS (GX * GY * 48)    // 6144
#define N_PIX 12582912.0

__device__ float g_part[N_BLOCKS];
__device__ unsigned int g_count;   // zero-init; self-resetting

// Gaussian window, sigma=1.5, ws=11, normalized. Function-local, constant
// indices after unroll -> FFMA with immediate multiplier (rt_SMSP=1).
#define DECL_GW()                                                        \
    const float GW[11] = {                                               \
        0.00102838f, 0.00759876f, 0.03600077f, 0.10936069f, 0.21300554f, \
        0.26601173f,                                                     \
        0.21300554f, 0.10936069f, 0.03600077f, 0.00759876f, 0.00102838f }

__device__ __forceinline__ float clip01(float v) {
    return fminf(fmaxf(v, 0.0f), 1.0f);   // fmaxf(NaN,0)=0 handles nan_to_num
}

extern __shared__ float smem_raw[];
// layout: sV[4][TY][SVS] | red[8]

__global__ __launch_bounds__(256, 2)
void ssim_main_kernel(const float* __restrict__ img1,
                      const float* __restrict__ img2,
                      float* __restrict__ out) {
    DECL_GW();
    float* sV0 = smem_raw;                 // vertically filtered: a
    float* sV1 = sV0 + TY * SVS;           // b
    float* sV2 = sV1 + TY * SVS;           // (a+b)^2
    float* sV3 = sV2 + TY * SVS;           // (a-b)^2
    float* red = sV3 + TY * SVS;
    __shared__ unsigned int s_is_last;
    __shared__ double dred[8];

    const int tid   = threadIdx.x;
    const int plane = blockIdx.z;
    const int cx0   = blockIdx.x * TX;
    const int cy0   = blockIdx.y * TY;
    const float* __restrict__ A = img1 + (size_t)plane * PLANE;
    const float* __restrict__ B = img2 + (size_t)plane * PLANE;

    // ---------------- Phase A: vertical 11-tap conv ----------------
    // 74 halo cols x 2 strips of 16 output rows = 148 work items.
    if (tid < 2 * HC) {
        const int col   = tid % HC;
        const int strip = tid / HC;
        const int r0    = strip * 16;
        const int gc    = cx0 + col - 5;
        const bool okc  = ((unsigned)gc < (unsigned)W_IMG);

        float acc0[16], acc1[16], acc2[16], acc3[16];
        #pragma unroll
        for (int r = 0; r < 16; r++) {
            acc0[r] = 0.0f; acc1[r] = 0.0f; acc2[r] = 0.0f; acc3[r] = 0.0f;
        }

        #pragma unroll
        for (int q = 0; q < 26; q++) {
            const int gr = cy0 + r0 + q - 5;
            float a = 0.0f, b = 0.0f;
            if (okc && (unsigned)gr < (unsigned)H_IMG) {
                const int idx = gr * W_IMG + gc;
                a = A[idx];
                b = B[idx];
            }
            a = clip01(a);
            b = clip01(b);
            const float s = a + b, d = a - b;
            const float p = s * s, m = d * d;
            #pragma unroll
            for (int rr = (q > 10 ? q - 10 : 0); rr <= (q < 15 ? q : 15); rr++) {
                const float w = GW[q - rr];          // immediate
                acc0[rr] = fmaf(a, w, acc0[rr]);
                acc1[rr] = fmaf(b, w, acc1[rr]);
                acc2[rr] = fmaf(p, w, acc2[rr]);
                acc3[rr] = fmaf(m, w, acc3[rr]);
            }
        }
        #pragma unroll
        for (int rr = 0; rr < 16; rr++) {
            const int o = (r0 + rr) * SVS + col;
            sV0[o] = acc0[rr];
            sV1[o] = acc1[rr];
            sV2[o] = acc2[rr];
            sV3[o] = acc3[rr];
        }
    }
    __syncthreads();

    // ---------------- Phase B: horizontal conv + SSIM ----------------
    // warp = 32 consecutive rows of one 8-col group; stride 75 -> CF LDS.
    const int orow = tid & 31;        // 0..31
    const int grp  = tid >> 5;        // 0..7
    const int base = orow * SVS + grp * 8;

    float acc0[8], acc1[8], acc2[8], acc3[8];
    #pragma unroll
    for (int o = 0; o < 8; o++) {
        acc0[o] = 0.0f; acc1[o] = 0.0f; acc2[o] = 0.0f; acc3[o] = 0.0f;
    }

    #pragma unroll
    for (int p = 0; p < 18; p++) {
        const float v0 = sV0[base + p];
        const float v1 = sV1[base + p];
        const float v2 = sV2[base + p];
        const float v3 = sV3[base + p];
        #pragma unroll
        for (int o = (p > 10 ? p - 10 : 0); o <= (p < 7 ? p : 7); o++) {
            const float w = GW[p - o];
            acc0[o] = fmaf(v0, w, acc0[o]);
            acc1[o] = fmaf(v1, w, acc1[o]);
            acc2[o] = fmaf(v2, w, acc2[o]);
            acc3[o] = fmaf(v3, w, acc3[o]);
        }
    }

    const float C1 = 0.000101f;   // 0.01^2 + 1e-6
    const float C2 = 0.000901f;   // 0.03^2 + 1e-6
    float lsum = 0.0f;
    #pragma unroll
    for (int o = 0; o < 8; o++) {
        const float mu1 = acc0[o], mu2 = acc1[o];
        const float Ep = acc2[o], Em = acc3[o];
        const float mu1s = mu1 * mu1;
        const float mu2s = mu2 * mu2;
        const float mu12 = mu1 * mu2;
        const float musum = mu1s + mu2s;
        const float ssum = fmaf(0.5f, Ep + Em, -musum);  // sigma1+sigma2
        const float s12  = fmaf(0.25f, Ep - Em, -mu12);  // sigma12
        const float num = fmaf(2.0f, mu12, C1) * fmaf(2.0f, s12, C2);
        const float den = (musum + C1) * (ssum + C2);
        lsum += __fdividef(num, den);
    }

    // ---------------- Block reduction -> partial sum ----------------
    #pragma unroll
    for (int off = 16; off > 0; off >>= 1)
        lsum += __shfl_xor_sync(0xffffffffu, lsum, off);

    const int warp = tid >> 5;
    const int lane = tid & 31;
    if (lane == 0) red[warp] = lsum;
    __syncthreads();

    const int bid = (blockIdx.z * GY + blockIdx.y) * GX + blockIdx.x;
    if (tid == 0) {
        float v = 0.0f;
        #pragma unroll
        for (int i = 0; i < 8; i++) v += red[i];
        g_part[bid] = v;
        __threadfence();
        const unsigned int c = atomicAdd(&g_count, 1u);
        s_is_last = (c == (unsigned)(N_BLOCKS - 1)) ? 1u : 0u;
    }
    __syncthreads();

    // ---------------- Last block: final reduction ----------------
    if (s_is_last) {
        const float4* p4 = (const float4*)g_part;    // 6144/4 = 1536
        double s = 0.0;
        for (int i = tid; i < N_BLOCKS / 4; i += 256) {
            const float4 v = p4[i];
            s += (double)v.x + (double)v.y + (double)v.z + (double)v.w;
        }
        #pragma unroll
        for (int off = 16; off > 0; off >>= 1)
            s += __shfl_xor_sync(0xffffffffu, s, off);
        if (lane == 0) dred[warp] = s;
        __syncthreads();
        if (warp == 0) {
            double v = (lane < 8) ? dred[lane] : 0.0;
            #pragma unroll
            for (int off = 4; off > 0; off >>= 1)
                v += __shfl_xor_sync(0xffffffffu, v, off);
            if (lane == 0) {
                out[0] = (float)(1.0 - v / N_PIX);
                g_count = 0;                 // reset for next replay
            }
        }
    }
}

extern "C" void kernel_launch(void* const* d_in, const int* in_sizes, int n_in,
                              void* d_out, int out_size) {
    const float* img1 = (const float*)d_in[0];
    const float* img2 = (const float*)d_in[1];
    float* out = (float*)d_out;

    const int smem_bytes = (4 * TY * SVS + 8) * 4;   // ~38.4 KB
    cudaFuncSetAttribute(ssim_main_kernel,
                         cudaFuncAttributeMaxDynamicSharedMemorySize,
                         smem_bytes);

    dim3 grid(GX, GY, 48);   // 8 x 16 x 48 = 6144 blocks
    ssim_main_kernel<<<grid, 256, smem_bytes>>>(img1, img2, out);
}

// round 16
// speedup vs baseline: 1.1699x; 1.1002x over previous
#include <cuda_runtime.h>
#include <cuda_bf16.h>

// SSIM loss: inputs (16,3,512,512) fp32 x2, output scalar fp32.
// Separable 11-tap Gaussian; 4 conv fields {a, b, (a+b)^2, (a-b)^2}:
//   sigma1+sigma2 = (Ep+Em)/2 - mu1^2 - mu2^2,  sigma12 = (Ep-Em)/4 - mu1*mu2.
//
// R15: R7 compute body + in-kernel last-block finalization, with
// __launch_bounds__(256, 3) to pin the register budget at 85 so the cold
// finalization tail cannot evict the 3rd resident block (R11's regression:
// tail pushed regs 72->95 -> 2 blocks/SM -> issue 61%).

#define W_IMG 512
#define H_IMG 512
#define PLANE (512 * 512)
#define TX 64
#define TY 32
#define HC (TX + 10)               // 74 halo cols
#define SVS 75                     // smem row stride (75 mod 32 = 11 -> CF)
#define GX (W_IMG / TX)            // 8
#define GY (H_IMG / TY)            // 16
#define N_BLOCKS (GX * GY * 48)    // 6144
#define N_PIX 12582912.0

__device__ float g_part[N_BLOCKS];
__device__ unsigned int g_count;   // zero-init; self-resetting

// Gaussian window, sigma=1.5, ws=11, normalized. Function-local, constant
// indices after unroll -> FFMA with immediate multiplier (rt_SMSP=1).
#define DECL_GW()                                                        \
    const float GW[11] = {                                               \
        0.00102838f, 0.00759876f, 0.03600077f, 0.10936069f, 0.21300554f, \
        0.26601173f,                                                     \
        0.21300554f, 0.10936069f, 0.03600077f, 0.00759876f, 0.00102838f }

__device__ __forceinline__ float clip01(float v) {
    return fminf(fmaxf(v, 0.0f), 1.0f);   // fmaxf(NaN,0)=0 handles nan_to_num
}

extern __shared__ float smem_raw[];
// layout: sV[4][TY][SVS] | red[8]

__global__ __launch_bounds__(256, 3)
void ssim_main_kernel(const float* __restrict__ img1,
                      const float* __restrict__ img2,
                      float* __restrict__ out) {
    DECL_GW();
    float* sV0 = smem_raw;                 // vertically filtered: a
    float* sV1 = sV0 + TY * SVS;           // b
    float* sV2 = sV1 + TY * SVS;           // (a+b)^2
    float* sV3 = sV2 + TY * SVS;           // (a-b)^2
    float* red = sV3 + TY * SVS;
    __shared__ unsigned int s_is_last;
    __shared__ double dred[8];

    const int tid   = threadIdx.x;
    const int plane = blockIdx.z;
    const int cx0   = blockIdx.x * TX;
    const int cy0   = blockIdx.y * TY;
    const float* __restrict__ A = img1 + (size_t)plane * PLANE;
    const float* __restrict__ B = img2 + (size_t)plane * PLANE;

    // ---------------- Phase A: vertical 11-tap conv ----------------
    // 74 halo cols x 2 strips of 16 output rows = 148 work items.
    if (tid < 2 * HC) {
        const int col   = tid % HC;
        const int strip = tid / HC;
        const int r0    = strip * 16;
        const int gc    = cx0 + col - 5;
        const bool okc  = ((unsigned)gc < (unsigned)W_IMG);

        float acc0[16], acc1[16], acc2[16], acc3[16];
        #pragma unroll
        for (int r = 0; r < 16; r++) {
            acc0[r] = 0.0f; acc1[r] = 0.0f; acc2[r] = 0.0f; acc3[r] = 0.0f;
        }

        #pragma unroll
        for (int q = 0; q < 26; q++) {
            const int gr = cy0 + r0 + q - 5;
            float a = 0.0f, b = 0.0f;
            if (okc && (unsigned)gr < (unsigned)H_IMG) {
                const int idx = gr * W_IMG + gc;
                a = A[idx];
                b = B[idx];
            }
            a = clip01(a);
            b = clip01(b);
            const float s = a + b, d = a - b;
            const float p = s * s, m = d * d;
            #pragma unroll
            for (int rr = (q > 10 ? q - 10 : 0); rr <= (q < 15 ? q : 15); rr++) {
                const float w = GW[q - rr];          // immediate
                acc0[rr] = fmaf(a, w, acc0[rr]);
                acc1[rr] = fmaf(b, w, acc1[rr]);
                acc2[rr] = fmaf(p, w, acc2[rr]);
                acc3[rr] = fmaf(m, w, acc3[rr]);
            }
        }
        #pragma unroll
        for (int rr = 0; rr < 16; rr++) {
            const int o = (r0 + rr) * SVS + col;
            sV0[o] = acc0[rr];
            sV1[o] = acc1[rr];
            sV2[o] = acc2[rr];
            sV3[o] = acc3[rr];
        }
    }
    __syncthreads();

    // ---------------- Phase B: horizontal conv + SSIM ----------------
    // warp = 32 consecutive rows of one 8-col group; stride 75 -> CF LDS.
    const int orow = tid & 31;        // 0..31
    const int grp  = tid >> 5;        // 0..7
    const int base = orow * SVS + grp * 8;

    float acc0[8], acc1[8], acc2[8], acc3[8];
    #pragma unroll
    for (int o = 0; o < 8; o++) {
        acc0[o] = 0.0f; acc1[o] = 0.0f; acc2[o] = 0.0f; acc3[o] = 0.0f;
    }

    #pragma unroll
    for (int p = 0; p < 18; p++) {
        const float v0 = sV0[base + p];
        const float v1 = sV1[base + p];
        const float v2 = sV2[base + p];
        const float v3 = sV3[base + p];
        #pragma unroll
        for (int o = (p > 10 ? p - 10 : 0); o <= (p < 7 ? p : 7); o++) {
            const float w = GW[p - o];
            acc0[o] = fmaf(v0, w, acc0[o]);
            acc1[o] = fmaf(v1, w, acc1[o]);
            acc2[o] = fmaf(v2, w, acc2[o]);
            acc3[o] = fmaf(v3, w, acc3[o]);
        }
    }

    const float C1 = 0.000101f;   // 0.01^2 + 1e-6
    const float C2 = 0.000901f;   // 0.03^2 + 1e-6
    float lsum = 0.0f;
    #pragma unroll
    for (int o = 0; o < 8; o++) {
        const float mu1 = acc0[o], mu2 = acc1[o];
        const float Ep = acc2[o], Em = acc3[o];
        const float mu1s = mu1 * mu1;
        const float mu2s = mu2 * mu2;
        const float mu12 = mu1 * mu2;
        const float musum = mu1s + mu2s;
        const float ssum = fmaf(0.5f, Ep + Em, -musum);  // sigma1+sigma2
        const float s12  = fmaf(0.25f, Ep - Em, -mu12);  // sigma12
        const float num = fmaf(2.0f, mu12, C1) * fmaf(2.0f, s12, C2);
        const float den = (musum + C1) * (ssum + C2);
        lsum += __fdividef(num, den);
    }

    // ---------------- Block reduction -> partial sum ----------------
    #pragma unroll
    for (int off = 16; off > 0; off >>= 1)
        lsum += __shfl_xor_sync(0xffffffffu, lsum, off);

    const int warp = tid >> 5;
    const int lane = tid & 31;
    if (lane == 0) red[warp] = lsum;
    __syncthreads();

    const int bid = (blockIdx.z * GY + blockIdx.y) * GX + blockIdx.x;
    if (tid == 0) {
        float v = 0.0f;
        #pragma unroll
        for (int i = 0; i < 8; i++) v += red[i];
        g_part[bid] = v;
        __threadfence();
        const unsigned int c = atomicAdd(&g_count, 1u);
        s_is_last = (c == (unsigned)(N_BLOCKS - 1)) ? 1u : 0u;
    }
    __syncthreads();

    // ---------------- Last block: final reduction (cold path) ----------------
    if (s_is_last) {
        const float4* p4 = (const float4*)g_part;    // 6144/4 = 1536
        double s = 0.0;
        for (int i = tid; i < N_BLOCKS / 4; i += 256) {
            const float4 v = p4[i];
            // pair-sum in float first: fewer live doubles in the tail frame
            const float s01 = v.x + v.y;
            const float s23 = v.z + v.w;
            s += (double)s01 + (double)s23;
        }
        #pragma unroll
        for (int off = 16; off > 0; off >>= 1)
            s += __shfl_xor_sync(0xffffffffu, s, off);
        if (lane == 0) dred[warp] = s;
        __syncthreads();
        if (warp == 0) {
            double v = (lane < 8) ? dred[lane] : 0.0;
            #pragma unroll
            for (int off = 4; off > 0; off >>= 1)
                v += __shfl_xor_sync(0xffffffffu, v, off);
            if (lane == 0) {
                out[0] = (float)(1.0 - v / N_PIX);
                g_count = 0;                 // reset for next replay
            }
        }
    }
}

extern "C" void kernel_launch(void* const* d_in, const int* in_sizes, int n_in,
                              void* d_out, int out_size) {
    const float* img1 = (const float*)d_in[0];
    const float* img2 = (const float*)d_in[1];
    float* out = (float*)d_out;

    const int smem_bytes = (4 * TY * SVS + 8) * 4;   // ~38.4 KB
    cudaFuncSetAttribute(ssim_main_kernel,
                         cudaFuncAttributeMaxDynamicSharedMemorySize,
                         smem_bytes);

    dim3 grid(GX, GY, 48);   // 8 x 16 x 48 = 6144 blocks
    ssim_main_kernel<<<grid, 256, smem_bytes>>>(img1, img2, out);
}

// round 17
// speedup vs baseline: 1.3204x; 1.1286x over previous
#include <cuda_runtime.h>
#include <cuda_bf16.h>

// SSIM loss: inputs (16,3,512,512) fp32 x2, output scalar fp32.
// Separable 11-tap Gaussian; 4 conv fields {a, b, (a+b)^2, (a-b)^2}:
//   sigma1+sigma2 = (Ep+Em)/2 - mu1^2 - mu2^2,  sigma12 = (Ep-Em)/4 - mu1*mu2.
//
// R16: fence-free fused finalization (partials travel through a double
// atomicAdd; acq_rel counter for last-block detection; atomicExch reads and
// resets the accumulator) + float2-paired smem (LDS.64/STS.64, conflict-free:
// slot = 11*lane mod 16). Compute body identical to the proven TX64/TY32
// FFMA-imm kernel; __launch_bounds__(256,3) keeps 3 blocks/SM.

#define W_IMG 512
#define H_IMG 512
#define PLANE (512 * 512)
#define TX 64
#define TY 32
#define HC (TX + 10)               // 74 halo cols
#define SVS 75                     // smem row stride in float2 units (odd)
#define GX (W_IMG / TX)            // 8
#define GY (H_IMG / TY)            // 16
#define N_BLOCKS (GX * GY * 48)    // 6144
#define N_PIX 12582912.0

__device__ double g_accum;         // zero-init; reset by last block each launch
__device__ unsigned int g_count;   // zero-init; reset by last block each launch

// Gaussian window, sigma=1.5, ws=11, normalized. Function-local, constant
// indices after unroll -> FFMA with immediate multiplier (rt_SMSP=1).
#define DECL_GW()                                                        \
    const float GW[11] = {                                               \
        0.00102838f, 0.00759876f, 0.03600077f, 0.10936069f, 0.21300554f, \
        0.26601173f,                                                     \
        0.21300554f, 0.10936069f, 0.03600077f, 0.00759876f, 0.00102838f }

__device__ __forceinline__ float clip01(float v) {
    return fminf(fmaxf(v, 0.0f), 1.0f);   // fmaxf(NaN,0)=0 handles nan_to_num
}

extern __shared__ float smem_raw[];
// layout: sV01 [TY][SVS] float2 | sV23 [TY][SVS] float2 | red[8]

__global__ __launch_bounds__(256, 3)
void ssim_main_kernel(const float* __restrict__ img1,
                      const float* __restrict__ img2,
                      float* __restrict__ out) {
    DECL_GW();
    float2* sV01 = (float2*)smem_raw;          // (a-filtered, b-filtered)
    float2* sV23 = sV01 + TY * SVS;            // ((a+b)^2-filtered, (a-b)^2-filtered)
    float*  red  = (float*)(sV23 + TY * SVS);

    const int tid   = threadIdx.x;
    const int plane = blockIdx.z;
    const int cx0   = blockIdx.x * TX;
    const int cy0   = blockIdx.y * TY;
    const float* __restrict__ A = img1 + (size_t)plane * PLANE;
    const float* __restrict__ B = img2 + (size_t)plane * PLANE;

    // ---------------- Phase A: vertical 11-tap conv ----------------
    // 74 halo cols x 2 strips of 16 output rows = 148 work items.
    if (tid < 2 * HC) {
        const int col   = tid % HC;
        const int strip = tid / HC;
        const int r0    = strip * 16;
        const int gc    = cx0 + col - 5;
        const bool okc  = ((unsigned)gc < (unsigned)W_IMG);

        float acc0[16], acc1[16], acc2[16], acc3[16];
        #pragma unroll
        for (int r = 0; r < 16; r++) {
            acc0[r] = 0.0f; acc1[r] = 0.0f; acc2[r] = 0.0f; acc3[r] = 0.0f;
        }

        #pragma unroll
        for (int q = 0; q < 26; q++) {
            const int gr = cy0 + r0 + q - 5;
            float a = 0.0f, b = 0.0f;
            if (okc && (unsigned)gr < (unsigned)H_IMG) {
                const int idx = gr * W_IMG + gc;
                a = A[idx];
                b = B[idx];
            }
            a = clip01(a);
            b = clip01(b);
            const float s = a + b, d = a - b;
            const float p = s * s, m = d * d;
            #pragma unroll
            for (int rr = (q > 10 ? q - 10 : 0); rr <= (q < 15 ? q : 15); rr++) {
                const float w = GW[q - rr];          // immediate
                acc0[rr] = fmaf(a, w, acc0[rr]);
                acc1[rr] = fmaf(b, w, acc1[rr]);
                acc2[rr] = fmaf(p, w, acc2[rr]);
                acc3[rr] = fmaf(m, w, acc3[rr]);
            }
        }
        #pragma unroll
        for (int rr = 0; rr < 16; rr++) {
            const int o = (r0 + rr) * SVS + col;
            sV01[o] = make_float2(acc0[rr], acc1[rr]);
            sV23[o] = make_float2(acc2[rr], acc3[rr]);
        }
    }
    __syncthreads();

    // ---------------- Phase B: horizontal conv + SSIM ----------------
    // warp = 32 consecutive rows of one 8-col group; LDS.64 conflict-free
    // (8B-slot = 11*lane mod 16, gcd(11,16)=1).
    const int orow = tid & 31;        // 0..31
    const int grp  = tid >> 5;        // 0..7
    const int base = orow * SVS + grp * 8;

    float acc0[8], acc1[8], acc2[8], acc3[8];
    #pragma unroll
    for (int o = 0; o < 8; o++) {
        acc0[o] = 0.0f; acc1[o] = 0.0f; acc2[o] = 0.0f; acc3[o] = 0.0f;
    }

    #pragma unroll
    for (int p = 0; p < 18; p++) {
        const float2 v01 = sV01[base + p];
        const float2 v23 = sV23[base + p];
        #pragma unroll
        for (int o = (p > 10 ? p - 10 : 0); o <= (p < 7 ? p : 7); o++) {
            const float w = GW[p - o];
            acc0[o] = fmaf(v01.x, w, acc0[o]);
            acc1[o] = fmaf(v01.y, w, acc1[o]);
            acc2[o] = fmaf(v23.x, w, acc2[o]);
            acc3[o] = fmaf(v23.y, w, acc3[o]);
        }
    }

    const float C1 = 0.000101f;   // 0.01^2 + 1e-6
    const float C2 = 0.000901f;   // 0.03^2 + 1e-6
    float lsum = 0.0f;
    #pragma unroll
    for (int o = 0; o < 8; o++) {
        const float mu1 = acc0[o], mu2 = acc1[o];
        const float Ep = acc2[o], Em = acc3[o];
        const float mu1s = mu1 * mu1;
        const float mu2s = mu2 * mu2;
        const float mu12 = mu1 * mu2;
        const float musum = mu1s + mu2s;
        const float ssum = fmaf(0.5f, Ep + Em, -musum);  // sigma1+sigma2
        const float s12  = fmaf(0.25f, Ep - Em, -mu12);  // sigma12
        const float num = fmaf(2.0f, mu12, C1) * fmaf(2.0f, s12, C2);
        const float den = (musum + C1) * (ssum + C2);
        lsum += __fdividef(num, den);
    }

    // ---------------- Block reduction ----------------
    #pragma unroll
    for (int off = 16; off > 0; off >>= 1)
        lsum += __shfl_xor_sync(0xffffffffu, lsum, off);

    const int warp = tid >> 5;
    const int lane = tid & 31;
    if (lane == 0) red[warp] = lsum;
    __syncthreads();

    // ---------------- Fence-free finalization (tid 0 only) ----------------
    if (tid == 0) {
        float v = 0.0f;
        #pragma unroll
        for (int i = 0; i < 8; i++) v += red[i];

        // Partial travels through the atomic: no publication fence needed.
        atomicAdd(&g_accum, (double)v);

        // acq_rel counter: release orders my accum-add before this; acquire
        // on the winning increment orders the exchange below after all adds.
        unsigned int c;
        asm volatile("atom.acq_rel.gpu.add.u32 %0, [%1], %2;"
                     : "=r"(c) : "l"(&g_count), "r"(1u) : "memory");

        if (c == (unsigned)(N_BLOCKS - 1)) {
            // Read final sum AND reset accumulator for the next replay.
            unsigned long long bits =
                atomicExch((unsigned long long*)&g_accum, 0ull);
            const double total = __longlong_as_double(bits);
            out[0] = (float)(1.0 - total / N_PIX);
            g_count = 0;                    // reset counter for next replay
        }
    }
}

extern "C" void kernel_launch(void* const* d_in, const int* in_sizes, int n_in,
                              void* d_out, int out_size) {
    const float* img1 = (const float*)d_in[0];
    const float* img2 = (const float*)d_in[1];
    float* out = (float*)d_out;

    const int smem_bytes = (2 * TY * SVS * 2 + 8) * 4;   // ~38.4 KB
    cudaFuncSetAttribute(ssim_main_kernel,
                         cudaFuncAttributeMaxDynamicSharedMemorySize,
                         smem_bytes);

    dim3 grid(GX, GY, 48);   // 8 x 16 x 48 = 6144 blocks
    ssim_main_kernel<<<grid, 256, smem_bytes>>>(img1, img2, out);
}